// round 8
// baseline (speedup 1.0000x reference)
#include <cuda_runtime.h>
#include <cuda_bf16.h>
#include <cstdint>

// Problem shape (fixed by the dataset): N=M=4096, DIM=8, TASKS=8
constexpr int NN   = 4096;
constexpr int MM   = 4096;
constexpr int DIMC = 8;
constexpr int TT   = 8;

constexpr int TR  = 32;     // rows per group (== warp size)
constexpr int TCW = 256;    // columns per tile (wide)
constexpr int TCS = 257;    // compact-tile stride (odd -> conflict-free)
constexpr int XT_STRIDE = 33;
constexpr int MAXG = 136;   // >= floor(4096/32) + (TASKS-1) = 135
constexpr int CNT_S = 129;  // prep count-array stride

// Scratch (no cudaMalloc allowed)
__device__ int   g_perm[MAXG * TR];   // row indices grouped by task, -1 = pad
__device__ int   g_gtask[MAXG];       // task id per group, -1 = unused
__device__ float g_inv2[TT * DIMC];   // -0.5*log2(e)/softplus(scale[t,t,d])^2
__device__ float g_v[TT];             // softplus(variance[t,t])
__device__ float g_u[NN * DIMC];      // -2*inv2[t_r][d]*x[r][d]
__device__ float g_A2[NN];            // sum_d inv2*x^2 + log2(v[t_r])
__device__ float g_B[TT * MM];        // B[t][c] = sum_d inv2[t][d]*xx[c][d]^2

__device__ __forceinline__ float softplus_f(float a) {
    return (a > 20.0f) ? a : log1pf(__expf(a));
}

// ---------------------------------------------------------------------------
// Prep (1 CTA, 1024 threads): atomic-free counting sort (ballot counts +
// shfl warp-scan) PLUS precompute of the rank-9 decomposition tables
// g_u / g_A2 / g_B (exponent = A_r + B_c + u_r . xx_c, log2-domain).
// ---------------------------------------------------------------------------
__global__ __launch_bounds__(1024) void rbf_prep(
    const int* __restrict__ i_task,
    const float* __restrict__ scale_raw,
    const float* __restrict__ var_raw,
    const float* __restrict__ x,
    const float* __restrict__ xx)
{
    __shared__ int s_cnt[TT * CNT_S];
    __shared__ int s_excl[TT * CNT_S];
    __shared__ int s_wt[TT][4];
    __shared__ int s_tot[TT];
    __shared__ int base[TT];
    __shared__ int gbase[TT];
    __shared__ int ngr[TT];

    const int tid  = threadIdx.x;
    const int lane = tid & 31;
    const int wid  = tid >> 5;

    if (tid < TT * DIMC) {
        const int t = tid / DIMC, d = tid % DIMC;
        const float s = softplus_f(scale_raw[t * (TT * DIMC) + t * DIMC + d]);
        g_inv2[tid] = -0.5f * 1.4426950408889634f / (s * s);  // log2(e) folded
    }
    if (tid < TT) g_v[tid] = softplus_f(var_raw[tid * TT + tid]);

    // ---- pass 1: per-chunk ballot counts + own rank-in-chunk ----
    int myt[NN / 1024];
    int myrank[NN / 1024];
#pragma unroll
    for (int j = 0; j < NN / 1024; j++) {
        const int t = i_task[j * 1024 + tid];
        myt[j] = t;
        const int chunk = j * 32 + wid;
        unsigned m_own = 0;
#pragma unroll
        for (int u = 0; u < TT; u++) {
            const unsigned m = __ballot_sync(0xffffffffu, t == u);
            if (lane == u) s_cnt[u * CNT_S + chunk] = __popc(m);
            if (t == u) m_own = m;
        }
        myrank[j] = __popc(m_own & ((1u << lane) - 1u));
    }
    __syncthreads();   // also publishes g_inv2 / g_v block-wide

    // ---- pass 2: 128-wide scan per task via shfl warp-scan ----
    {
        const int u = tid >> 7;
        const int c = tid & 127;
        const int wir = c >> 5;
        const int orig = s_cnt[u * CNT_S + c];
        int v = orig;
#pragma unroll
        for (int off = 1; off < 32; off <<= 1) {
            const int tv = __shfl_up_sync(0xffffffffu, v, off);
            if (lane >= off) v += tv;
        }
        if (lane == 31) s_wt[u][wir] = v;
        __syncthreads();
        int add = 0;
#pragma unroll
        for (int j2 = 0; j2 < 3; j2++) if (wir > j2) add += s_wt[u][j2];
        s_excl[u * CNT_S + c] = v + add - orig;
        if (c == 127) s_tot[u] = v + add;
    }
    __syncthreads();

    // ---- pass 3: per-task bases + group table ----
    if (tid < TT) {
        int eb = 0, gb = 0;
        for (int u = 0; u < tid; u++) {
            const int g = (s_tot[u] + TR - 1) / TR;
            gb += g; eb += g * TR;
        }
        base[tid]  = eb;
        gbase[tid] = gb;
        ngr[tid]   = (s_tot[tid] + TR - 1) / TR;
    }
    __syncthreads();

    if (tid < MAXG) {
        int val = -1;
#pragma unroll
        for (int t = 0; t < TT; t++)
            if (tid >= gbase[t] && tid < gbase[t] + ngr[t]) val = t;
        g_gtask[tid] = val;
    }

    // pad-only init: at most 31 slots per task
    if (tid < TT * TR) {
        const int tt = tid >> 5, k = tid & 31;
        const int c = s_tot[tt];
        if (k < ngr[tt] * TR - c) g_perm[base[tt] + c + k] = -1;
    }

    // ---- pass 4: direct scatter, no atomics ----
#pragma unroll
    for (int j = 0; j < NN / 1024; j++) {
        const int r = j * 1024 + tid;
        const int t = myt[j];
        const int chunk = j * 32 + wid;
        g_perm[base[t] + s_excl[t * CNT_S + chunk] + myrank[j]] = r;
    }

    // ---- pass 5: rank-9 tables (independent; after bar1 so inv2/v visible) --
#pragma unroll
    for (int j = 0; j < NN / 1024; j++) {
        const int r = j * 1024 + tid;
        const int t = myt[j];
        const float4 a = *(const float4*)&x[r * DIMC + 0];
        const float4 b = *(const float4*)&x[r * DIMC + 4];
        float iv[DIMC];
#pragma unroll
        for (int d = 0; d < DIMC; d++) iv[d] = g_inv2[t * DIMC + d];
        float A = iv[0] * a.x * a.x;
        A = fmaf(iv[1], a.y * a.y, A); A = fmaf(iv[2], a.z * a.z, A);
        A = fmaf(iv[3], a.w * a.w, A); A = fmaf(iv[4], b.x * b.x, A);
        A = fmaf(iv[5], b.y * b.y, A); A = fmaf(iv[6], b.z * b.z, A);
        A = fmaf(iv[7], b.w * b.w, A);
        g_A2[r] = A + log2f(g_v[t]);
        float4 ua = make_float4(-2.f * iv[0] * a.x, -2.f * iv[1] * a.y,
                                -2.f * iv[2] * a.z, -2.f * iv[3] * a.w);
        float4 ub = make_float4(-2.f * iv[4] * b.x, -2.f * iv[5] * b.y,
                                -2.f * iv[6] * b.z, -2.f * iv[7] * b.w);
        *(float4*)&g_u[r * DIMC + 0] = ua;
        *(float4*)&g_u[r * DIMC + 4] = ub;
    }
#pragma unroll
    for (int j = 0; j < MM / 1024; j++) {
        const int c = j * 1024 + tid;
        const float4 a = *(const float4*)&xx[c * DIMC + 0];
        const float4 b = *(const float4*)&xx[c * DIMC + 4];
        const float q0 = a.x * a.x, q1 = a.y * a.y, q2 = a.z * a.z, q3 = a.w * a.w;
        const float q4 = b.x * b.x, q5 = b.y * b.y, q6 = b.z * b.z, q7 = b.w * b.w;
#pragma unroll
        for (int t = 0; t < TT; t++) {
            float B = g_inv2[t * DIMC + 0] * q0;
            B = fmaf(g_inv2[t * DIMC + 1], q1, B);
            B = fmaf(g_inv2[t * DIMC + 2], q2, B);
            B = fmaf(g_inv2[t * DIMC + 3], q3, B);
            B = fmaf(g_inv2[t * DIMC + 4], q4, B);
            B = fmaf(g_inv2[t * DIMC + 5], q5, B);
            B = fmaf(g_inv2[t * DIMC + 6], q6, B);
            B = fmaf(g_inv2[t * DIMC + 7], q7, B);
            g_B[t * MM + c] = B;
        }
    }
}

// ---------------------------------------------------------------------------
// Main: one CTA = 32 rows (same task t) x 256 columns.
//  - per-warp own-ballot compaction of matched columns (CNT ~ 32)
//  - exponent = A_r + B_c + u_r . xx_c : 8 FFMA + 1 FADD + EX2 per cell
//  - compact smem staging of matched values only; zeros assembled in
//    registers at write time -> coalesced 512B STG.128 segments
// ---------------------------------------------------------------------------
__global__ __launch_bounds__(256) void rbf_main(
    const float* __restrict__ xx,
    const int*  __restrict__ ii,
    float* __restrict__ out)
{
    const int g = blockIdx.y;
    const int t = g_gtask[g];
    if (t < 0) return;

    const int c0   = blockIdx.x * TCW;
    const int tid  = threadIdx.x;
    const int lane = tid & 31;
    const int w    = tid >> 5;

    __shared__ __align__(16) int s_midx[TCW];  // col -> compact idx or -1
    __shared__ int   s_mcol[TCW];              // compact idx -> col
    __shared__ int   s_wcnt[8];
    __shared__ int   s_rows[TR];
    __shared__ float s_A[TR];
    __shared__ float s_uT[DIMC * XT_STRIDE];   // u transposed [d][row]
    __shared__ float s_xc[TCW * DIMC];         // compact xx rows
    __shared__ float s_B[TCW];                 // compact B values
    __shared__ float s_tc[TR * TCS];           // compact values [row][m]

    // per-warp column check: warp w owns cols w*32..w*32+31, lane = col
    const int col = w * 32 + lane;
    const bool match = (ii[c0 + col] == t);
    const unsigned bal = __ballot_sync(0xffffffffu, match);
    if (lane == 0) s_wcnt[w] = __popc(bal);

    // u-row + A gather (8 threads per row, broadcast perm read)
    {
        const int r = tid >> 3;
        const int d = tid & 7;
        const int row = g_perm[g * TR + r];
        if (d == 0) {
            s_rows[r] = row;
            s_A[r] = (row >= 0) ? g_A2[row] : 0.0f;
        }
        s_uT[d * XT_STRIDE + r] = (row >= 0) ? g_u[row * DIMC + d] : 0.0f;
    }
    __syncthreads();

    int basew = 0, CNT = 0;
#pragma unroll
    for (int u = 0; u < 8; u++) {
        const int cu = s_wcnt[u];
        if (u < w) basew += cu;
        CNT += cu;
    }
    const int rank = __popc(bal & ((1u << lane) - 1u));
    const int midx = match ? basew + rank : -1;
    s_midx[col] = midx;
    if (match) s_mcol[midx] = col;
    __syncthreads();

    // gather xx + B for matched columns only
    {
        const int d = tid & 7;
        for (int m = tid >> 3; m < CNT; m += 32) {
            const int c = s_mcol[m];
            s_xc[m * DIMC + d] = xx[(c0 + c) * DIMC + d];
            if (d == 0) s_B[m] = g_B[t * MM + c0 + c];
        }
    }
    __syncthreads();

    // compute: lanes = rows, warp w handles compact cols m = w, w+8, ...
    if (CNT > 0) {
        const float A = s_A[lane];
        float u0 = s_uT[0 * XT_STRIDE + lane], u1 = s_uT[1 * XT_STRIDE + lane];
        float u2 = s_uT[2 * XT_STRIDE + lane], u3 = s_uT[3 * XT_STRIDE + lane];
        float u4 = s_uT[4 * XT_STRIDE + lane], u5 = s_uT[5 * XT_STRIDE + lane];
        float u6 = s_uT[6 * XT_STRIDE + lane], u7 = s_uT[7 * XT_STRIDE + lane];

        for (int m = w; m < CNT; m += 8) {
            const float4 xa = *(const float4*)&s_xc[m * DIMC + 0];  // broadcast
            const float4 xb = *(const float4*)&s_xc[m * DIMC + 4];
            float sum = fmaf(u0, xa.x, A);
            sum = fmaf(u1, xa.y, sum);
            sum = fmaf(u2, xa.z, sum);
            sum = fmaf(u3, xa.w, sum);
            sum = fmaf(u4, xb.x, sum);
            sum = fmaf(u5, xb.y, sum);
            sum = fmaf(u6, xb.z, sum);
            sum = fmaf(u7, xb.w, sum);
            // banks (lane + m) % 32 -> conflict-free
            s_tc[lane * TCS + m] = exp2f(sum + s_B[m]);
        }
    }
    __syncthreads();

    // write: warp w -> rows 4w..4w+3; 2 chunks of 128 cols, 512B STG.128 each
#pragma unroll
    for (int ch = 0; ch < 2; ch++) {
        const int4 mi = ((const int4*)s_midx)[ch * 32 + lane];  // conflict-free
#pragma unroll
        for (int rr = 0; rr < 4; rr++) {
            const int r = w * 4 + rr;
            const int row = s_rows[r];
            if (row >= 0) {
                float4 o = make_float4(0.f, 0.f, 0.f, 0.f);
                const int rb = r * TCS;
                if (mi.x >= 0) o.x = s_tc[rb + mi.x];  // distinct midx -> no conflicts
                if (mi.y >= 0) o.y = s_tc[rb + mi.y];
                if (mi.z >= 0) o.z = s_tc[rb + mi.z];
                if (mi.w >= 0) o.w = s_tc[rb + mi.w];
                *(float4*)&out[(long)row * MM + c0 + ch * 128 + lane * 4] = o;
            }
        }
    }
}

// ---------------------------------------------------------------------------
extern "C" void kernel_launch(void* const* d_in, const int* in_sizes, int n_in,
                              void* d_out, int out_size)
{
    const float* x     = (const float*)d_in[0];
    const float* xx    = (const float*)d_in[1];
    const float* scale = (const float*)d_in[2];
    const float* var   = (const float*)d_in[3];
    const int*   i_t   = (const int*)d_in[4];
    const int*   ii_t  = (const int*)d_in[5];
    float* out = (float*)d_out;

    rbf_prep<<<1, 1024>>>(i_t, scale, var, x, xx);

    dim3 grid(MM / TCW, MAXG);
    rbf_main<<<grid, 256>>>(xx, ii_t, out);
}

// round 10
// speedup vs baseline: 1.2339x; 1.2339x over previous
#include <cuda_runtime.h>
#include <cuda_bf16.h>
#include <cstdint>

// Problem shape (fixed by the dataset): N=M=4096, DIM=8, TASKS=8
constexpr int NN   = 4096;
constexpr int MM   = 4096;
constexpr int DIMC = 8;
constexpr int TT   = 8;

constexpr int TR  = 32;     // rows per group (== warp size)
constexpr int TCW = 128;    // columns per tile -> CNT <= 128 guaranteed
constexpr int TCS = 129;    // compact-tile stride (odd -> conflict-free)
constexpr int XT_STRIDE = 33;
constexpr int MAXG = 136;   // >= floor(4096/32) + (TASKS-1) = 135
constexpr int CNT_S = 129;  // sort count-array stride

// Scratch (no cudaMalloc allowed)
__device__ int   g_perm[MAXG * TR];   // row indices grouped by task, -1 = pad
__device__ int   g_gtask[MAXG];       // task id per group, -1 = unused
__device__ float g_u[NN * DIMC];      // -2*inv2[t_r][d]*x[r][d]
__device__ float g_A2[NN];            // sum_d inv2*x^2 + log2(v[t_r])
__device__ float g_B[TT * MM];        // B[t][c] = sum_d inv2[t][d]*xx[c][d]^2

__device__ __forceinline__ float softplus_f(float a) {
    return (a > 20.0f) ? a : log1pf(__expf(a));
}

// ---------------------------------------------------------------------------
// Sort (1 CTA, 1024 threads): atomic-free counting sort of rows by task
// (ballot counts + shfl warp-scan + direct scatter). Nothing else.
// ---------------------------------------------------------------------------
__global__ __launch_bounds__(1024) void rbf_sort(const int* __restrict__ i_task)
{
    __shared__ int s_cnt[TT * CNT_S];
    __shared__ int s_excl[TT * CNT_S];
    __shared__ int s_wt[TT][4];
    __shared__ int s_tot[TT];
    __shared__ int base[TT];
    __shared__ int gbase[TT];
    __shared__ int ngr[TT];

    const int tid  = threadIdx.x;
    const int lane = tid & 31;
    const int wid  = tid >> 5;

    // ---- pass 1: per-chunk ballot counts + own rank-in-chunk ----
    int myt[NN / 1024];
    int myrank[NN / 1024];
#pragma unroll
    for (int j = 0; j < NN / 1024; j++) {
        const int t = i_task[j * 1024 + tid];
        myt[j] = t;
        const int chunk = j * 32 + wid;
        unsigned m_own = 0;
#pragma unroll
        for (int u = 0; u < TT; u++) {
            const unsigned m = __ballot_sync(0xffffffffu, t == u);
            if (lane == u) s_cnt[u * CNT_S + chunk] = __popc(m);
            if (t == u) m_own = m;
        }
        myrank[j] = __popc(m_own & ((1u << lane) - 1u));
    }
    __syncthreads();

    // ---- pass 2: 128-wide scan per task via shfl warp-scan ----
    {
        const int u = tid >> 7;
        const int c = tid & 127;
        const int wir = c >> 5;
        const int orig = s_cnt[u * CNT_S + c];
        int v = orig;
#pragma unroll
        for (int off = 1; off < 32; off <<= 1) {
            const int tv = __shfl_up_sync(0xffffffffu, v, off);
            if (lane >= off) v += tv;
        }
        if (lane == 31) s_wt[u][wir] = v;
        __syncthreads();
        int add = 0;
#pragma unroll
        for (int j2 = 0; j2 < 3; j2++) if (wir > j2) add += s_wt[u][j2];
        s_excl[u * CNT_S + c] = v + add - orig;
        if (c == 127) s_tot[u] = v + add;
    }
    __syncthreads();

    // ---- pass 3: per-task bases + group table ----
    if (tid < TT) {
        int eb = 0, gb = 0;
        for (int u = 0; u < tid; u++) {
            const int g = (s_tot[u] + TR - 1) / TR;
            gb += g; eb += g * TR;
        }
        base[tid]  = eb;
        gbase[tid] = gb;
        ngr[tid]   = (s_tot[tid] + TR - 1) / TR;
    }
    __syncthreads();

    if (tid < MAXG) {
        int val = -1;
#pragma unroll
        for (int t = 0; t < TT; t++)
            if (tid >= gbase[t] && tid < gbase[t] + ngr[t]) val = t;
        g_gtask[tid] = val;
    }

    // pad-only init: at most 31 slots per task
    if (tid < TT * TR) {
        const int tt = tid >> 5, k = tid & 31;
        const int c = s_tot[tt];
        if (k < ngr[tt] * TR - c) g_perm[base[tt] + c + k] = -1;
    }

    // ---- pass 4: direct scatter, no atomics ----
#pragma unroll
    for (int j = 0; j < NN / 1024; j++) {
        const int r = j * 1024 + tid;
        const int t = myt[j];
        const int chunk = j * 32 + wid;
        g_perm[base[t] + s_excl[t * CNT_S + chunk] + myrank[j]] = r;
    }
}

// ---------------------------------------------------------------------------
// Tables (grid-parallel, 32 CTAs x 256 thr): rank-9 decomposition tables.
//   exponent(r,c) = A_r + B_{t,c} + u_r . xx_c   (log2 domain, v folded in A)
// ---------------------------------------------------------------------------
__global__ __launch_bounds__(256) void rbf_tables(
    const float* __restrict__ scale_raw,
    const float* __restrict__ var_raw,
    const float* __restrict__ x,
    const float* __restrict__ xx,
    const int*  __restrict__ i_task)
{
    __shared__ float s_inv2[TT * DIMC];
    __shared__ float s_lv[TT];
    const int tid = threadIdx.x;

    if (tid < TT * DIMC) {
        const int t = tid / DIMC, d = tid % DIMC;
        const float s = softplus_f(scale_raw[t * (TT * DIMC) + t * DIMC + d]);
        s_inv2[tid] = -0.5f * 1.4426950408889634f / (s * s);  // log2(e) folded
    }
    if (tid < TT) s_lv[tid] = log2f(softplus_f(var_raw[tid * TT + tid]));
    __syncthreads();

    if (tid < 128) {
        // rows: g_u, g_A2
        const int r = blockIdx.x * 128 + tid;
        const int t = i_task[r];
        const float4 a = *(const float4*)&x[r * DIMC + 0];
        const float4 b = *(const float4*)&x[r * DIMC + 4];
        float iv[DIMC];
#pragma unroll
        for (int d = 0; d < DIMC; d++) iv[d] = s_inv2[t * DIMC + d];
        float A = iv[0] * a.x * a.x;
        A = fmaf(iv[1], a.y * a.y, A); A = fmaf(iv[2], a.z * a.z, A);
        A = fmaf(iv[3], a.w * a.w, A); A = fmaf(iv[4], b.x * b.x, A);
        A = fmaf(iv[5], b.y * b.y, A); A = fmaf(iv[6], b.z * b.z, A);
        A = fmaf(iv[7], b.w * b.w, A);
        g_A2[r] = A + s_lv[t];
        *(float4*)&g_u[r * DIMC + 0] =
            make_float4(-2.f * iv[0] * a.x, -2.f * iv[1] * a.y,
                        -2.f * iv[2] * a.z, -2.f * iv[3] * a.w);
        *(float4*)&g_u[r * DIMC + 4] =
            make_float4(-2.f * iv[4] * b.x, -2.f * iv[5] * b.y,
                        -2.f * iv[6] * b.z, -2.f * iv[7] * b.w);
    } else {
        // cols: g_B for all 8 tasks
        const int c = blockIdx.x * 128 + (tid - 128);
        const float4 a = *(const float4*)&xx[c * DIMC + 0];
        const float4 b = *(const float4*)&xx[c * DIMC + 4];
        const float q0 = a.x * a.x, q1 = a.y * a.y, q2 = a.z * a.z, q3 = a.w * a.w;
        const float q4 = b.x * b.x, q5 = b.y * b.y, q6 = b.z * b.z, q7 = b.w * b.w;
#pragma unroll
        for (int t = 0; t < TT; t++) {
            float B = s_inv2[t * DIMC + 0] * q0;
            B = fmaf(s_inv2[t * DIMC + 1], q1, B);
            B = fmaf(s_inv2[t * DIMC + 2], q2, B);
            B = fmaf(s_inv2[t * DIMC + 3], q3, B);
            B = fmaf(s_inv2[t * DIMC + 4], q4, B);
            B = fmaf(s_inv2[t * DIMC + 5], q5, B);
            B = fmaf(s_inv2[t * DIMC + 6], q6, B);
            B = fmaf(s_inv2[t * DIMC + 7], q7, B);
            g_B[t * MM + c] = B;
        }
    }
}

// ---------------------------------------------------------------------------
// Main: one CTA = 32 rows (same task t) x 128 columns. 8 CTAs/SM.
//  - per-warp own-ballot compaction (warps 0-3 own 32 cols each, CNT <= 128)
//  - exponent = A_r + B_c + u_r . xx_c : 8 FFMA + FADD + EX2 per matched cell
//  - compact smem staging; zeros assembled in registers -> 512B STG.128
// ---------------------------------------------------------------------------
__global__ __launch_bounds__(256, 8) void rbf_main(
    const float* __restrict__ xx,
    const int*  __restrict__ ii,
    float* __restrict__ out)
{
    const int g = blockIdx.y;
    const int t = g_gtask[g];
    if (t < 0) return;

    const int c0   = blockIdx.x * TCW;
    const int tid  = threadIdx.x;
    const int lane = tid & 31;
    const int w    = tid >> 5;

    __shared__ __align__(16) int s_midx[TCW];  // col -> compact idx or -1
    __shared__ int   s_mcol[TCW];              // compact idx -> col
    __shared__ int   s_wcnt[4];
    __shared__ int   s_rows[TR];
    __shared__ float s_A[TR];
    __shared__ float s_uT[DIMC * XT_STRIDE];   // u transposed [d][row]
    __shared__ float s_xc[TCW * DIMC];         // compact xx rows (4 KB)
    __shared__ float s_B[TCW];                 // compact B values
    __shared__ float s_tc[TR * TCS];           // compact values [row][m] (16.5 KB)

    // warps 0-3: column match check (warp w owns cols w*32..w*32+31)
    unsigned bal = 0;
    bool match = false;
    if (w < 4) {
        const int col = w * 32 + lane;
        match = (ii[c0 + col] == t);
        bal = __ballot_sync(0xffffffffu, match);
        if (lane == 0) s_wcnt[w] = __popc(bal);
    }

    // u-row + A gather (8 threads per row, broadcast perm read)
    {
        const int r = tid >> 3;
        const int d = tid & 7;
        const int row = g_perm[g * TR + r];
        if (d == 0) {
            s_rows[r] = row;
            s_A[r] = (row >= 0) ? g_A2[row] : 0.0f;
        }
        s_uT[d * XT_STRIDE + r] = (row >= 0) ? g_u[row * DIMC + d] : 0.0f;
    }
    __syncthreads();

    const int b0 = s_wcnt[0], b1 = s_wcnt[1], b2 = s_wcnt[2], b3 = s_wcnt[3];
    const int CNT = b0 + b1 + b2 + b3;
    if (w < 4) {
        const int col = w * 32 + lane;
        const int basew = (w >= 1 ? b0 : 0) + (w >= 2 ? b1 : 0) + (w >= 3 ? b2 : 0);
        const int midx = match ? basew + __popc(bal & ((1u << lane) - 1u)) : -1;
        s_midx[col] = midx;
        if (match) s_mcol[midx] = col;
    }
    __syncthreads();

    // gather xx + B for matched columns only (CNT*36B instead of 4.5KB)
    {
        const int d = tid & 7;
        for (int m = tid >> 3; m < CNT; m += 32) {
            const int c = s_mcol[m];
            s_xc[m * DIMC + d] = xx[(c0 + c) * DIMC + d];
            if (d == 0) s_B[m] = g_B[t * MM + c0 + c];
        }
    }
    __syncthreads();

    // compute: lanes = rows, warp w handles compact cols m = w, w+8, ...
    if (CNT > 0) {
        const float A = s_A[lane];
        const float u0 = s_uT[0 * XT_STRIDE + lane], u1 = s_uT[1 * XT_STRIDE + lane];
        const float u2 = s_uT[2 * XT_STRIDE + lane], u3 = s_uT[3 * XT_STRIDE + lane];
        const float u4 = s_uT[4 * XT_STRIDE + lane], u5 = s_uT[5 * XT_STRIDE + lane];
        const float u6 = s_uT[6 * XT_STRIDE + lane], u7 = s_uT[7 * XT_STRIDE + lane];

        for (int m = w; m < CNT; m += 8) {
            const float4 xa = *(const float4*)&s_xc[m * DIMC + 0];  // broadcast
            const float4 xb = *(const float4*)&s_xc[m * DIMC + 4];
            float sum = fmaf(u0, xa.x, A);
            sum = fmaf(u1, xa.y, sum);
            sum = fmaf(u2, xa.z, sum);
            sum = fmaf(u3, xa.w, sum);
            sum = fmaf(u4, xb.x, sum);
            sum = fmaf(u5, xb.y, sum);
            sum = fmaf(u6, xb.z, sum);
            sum = fmaf(u7, xb.w, sum);
            // banks (lane + m) % 32 -> conflict-free
            s_tc[lane * TCS + m] = exp2f(sum + s_B[m]);
        }
    }
    __syncthreads();

    // write: warp w -> rows 4w..4w+3; lane -> cols 4*lane..4*lane+3
    const int4 mi = ((const int4*)s_midx)[lane];  // LDS.128, conflict-free
#pragma unroll
    for (int rr = 0; rr < 4; rr++) {
        const int r = w * 4 + rr;
        const int row = s_rows[r];
        if (row >= 0) {
            float4 o = make_float4(0.f, 0.f, 0.f, 0.f);
            const int rb = r * TCS;
            if (mi.x >= 0) o.x = s_tc[rb + mi.x];  // distinct midx -> no conflicts
            if (mi.y >= 0) o.y = s_tc[rb + mi.y];
            if (mi.z >= 0) o.z = s_tc[rb + mi.z];
            if (mi.w >= 0) o.w = s_tc[rb + mi.w];
            *(float4*)&out[(long)row * MM + c0 + lane * 4] = o;
        }
    }
}

// ---------------------------------------------------------------------------
extern "C" void kernel_launch(void* const* d_in, const int* in_sizes, int n_in,
                              void* d_out, int out_size)
{
    const float* x     = (const float*)d_in[0];
    const float* xx    = (const float*)d_in[1];
    const float* scale = (const float*)d_in[2];
    const float* var   = (const float*)d_in[3];
    const int*   i_t   = (const int*)d_in[4];
    const int*   ii_t  = (const int*)d_in[5];
    float* out = (float*)d_out;

    rbf_sort<<<1, 1024>>>(i_t);
    rbf_tables<<<32, 256>>>(scale, var, x, xx, i_t);

    dim3 grid(MM / TCW, MAXG);
    rbf_main<<<grid, 256>>>(xx, ii_t, out);
}

// round 11
// speedup vs baseline: 1.2893x; 1.0449x over previous
#include <cuda_runtime.h>
#include <cuda_bf16.h>
#include <cstdint>

// Problem shape (fixed by the dataset): N=M=4096, DIM=8, TASKS=8
constexpr int NN   = 4096;
constexpr int MM   = 4096;
constexpr int DIMC = 8;
constexpr int TT   = 8;

constexpr int TR  = 64;     // rows per group (2 warps worth)
constexpr int TCW = 128;    // columns per tile
constexpr int TCS = 129;    // compact-tile stride (odd -> conflict-free)
constexpr int UT_S = 65;    // u-transposed stride
constexpr int MAXG = 71;    // >= floor(4096/64) + (TASKS-1) = 71
constexpr int CNT_S = 129;  // sort count-array stride

// Scratch (no cudaMalloc allowed)
__device__ int   g_perm[MAXG * TR];   // row indices grouped by task, -1 = pad
__device__ int   g_gtask[MAXG];       // task id per group, -1 = unused
__device__ float g_u[NN * DIMC];      // -2*inv2[t_r][d]*x[r][d]
__device__ float g_A2[NN];            // sum_d inv2*x^2 + log2(v[t_r])
__device__ float g_B[TT * MM];        // B[t][c] = sum_d inv2[t][d]*xx[c][d]^2

__device__ __forceinline__ float softplus_f(float a) {
    return (a > 20.0f) ? a : log1pf(__expf(a));
}

// ---------------------------------------------------------------------------
// Prep (9 CTAs x 1024 thr): CTA 8 = atomic-free counting sort (match_any +
// shfl warp-scan); CTAs 0-7 = rank-9 tables (g_u/g_A2/g_B), fully parallel.
// Tables work hides inside the sort's latency shadow.
// ---------------------------------------------------------------------------
__global__ __launch_bounds__(1024) void rbf_prep(
    const int* __restrict__ i_task,
    const float* __restrict__ scale_raw,
    const float* __restrict__ var_raw,
    const float* __restrict__ x,
    const float* __restrict__ xx)
{
    const int tid = threadIdx.x;

    if (blockIdx.x < 8) {
        // ================= tables CTAs =================
        __shared__ float s_inv2[TT * DIMC];
        __shared__ float s_lv[TT];
        if (tid < TT * DIMC) {
            const int t = tid / DIMC, d = tid % DIMC;
            const float s = softplus_f(scale_raw[t * (TT * DIMC) + t * DIMC + d]);
            s_inv2[tid] = -0.5f * 1.4426950408889634f / (s * s);  // log2(e) folded
        }
        if (tid < TT) s_lv[tid] = log2f(softplus_f(var_raw[tid * TT + tid]));
        __syncthreads();

        if (tid < 512) {
            // rows: g_u, g_A2
            const int r = blockIdx.x * 512 + tid;
            const int t = i_task[r];
            const float4 a = *(const float4*)&x[r * DIMC + 0];
            const float4 b = *(const float4*)&x[r * DIMC + 4];
            float iv[DIMC];
#pragma unroll
            for (int d = 0; d < DIMC; d++) iv[d] = s_inv2[t * DIMC + d];
            float A = iv[0] * a.x * a.x;
            A = fmaf(iv[1], a.y * a.y, A); A = fmaf(iv[2], a.z * a.z, A);
            A = fmaf(iv[3], a.w * a.w, A); A = fmaf(iv[4], b.x * b.x, A);
            A = fmaf(iv[5], b.y * b.y, A); A = fmaf(iv[6], b.z * b.z, A);
            A = fmaf(iv[7], b.w * b.w, A);
            g_A2[r] = A + s_lv[t];
            *(float4*)&g_u[r * DIMC + 0] =
                make_float4(-2.f * iv[0] * a.x, -2.f * iv[1] * a.y,
                            -2.f * iv[2] * a.z, -2.f * iv[3] * a.w);
            *(float4*)&g_u[r * DIMC + 4] =
                make_float4(-2.f * iv[4] * b.x, -2.f * iv[5] * b.y,
                            -2.f * iv[6] * b.z, -2.f * iv[7] * b.w);
        } else {
            // cols: g_B for all 8 tasks
            const int c = blockIdx.x * 512 + (tid - 512);
            const float4 a = *(const float4*)&xx[c * DIMC + 0];
            const float4 b = *(const float4*)&xx[c * DIMC + 4];
            const float q0 = a.x * a.x, q1 = a.y * a.y, q2 = a.z * a.z, q3 = a.w * a.w;
            const float q4 = b.x * b.x, q5 = b.y * b.y, q6 = b.z * b.z, q7 = b.w * b.w;
#pragma unroll
            for (int t = 0; t < TT; t++) {
                float B = s_inv2[t * DIMC + 0] * q0;
                B = fmaf(s_inv2[t * DIMC + 1], q1, B);
                B = fmaf(s_inv2[t * DIMC + 2], q2, B);
                B = fmaf(s_inv2[t * DIMC + 3], q3, B);
                B = fmaf(s_inv2[t * DIMC + 4], q4, B);
                B = fmaf(s_inv2[t * DIMC + 5], q5, B);
                B = fmaf(s_inv2[t * DIMC + 6], q6, B);
                B = fmaf(s_inv2[t * DIMC + 7], q7, B);
                g_B[t * MM + c] = B;
            }
        }
        return;
    }

    // ================= sort CTA =================
    __shared__ int s_cnt[TT * CNT_S];
    __shared__ int s_excl[TT * CNT_S];
    __shared__ int s_wt[TT][4];
    __shared__ int s_tot[TT];
    __shared__ int base[TT];
    __shared__ int gbase[TT];
    __shared__ int ngr[TT];

    const int lane = tid & 31;
    const int wid  = tid >> 5;

    // zero counts (match_any stores only present tasks)
    if (tid < TT * CNT_S) s_cnt[tid] = 0;
    if (tid >= 1024 - 8) s_cnt[TT * CNT_S - (1024 - tid)] = 0;  // tail (1032>1024)
    __syncthreads();

    // ---- pass 1: per-chunk counts via match_any + own rank-in-chunk ----
    int myt[NN / 1024];
    int myrank[NN / 1024];
#pragma unroll
    for (int j = 0; j < NN / 1024; j++) {
        const int t = i_task[j * 1024 + tid];
        myt[j] = t;
        const int chunk = j * 32 + wid;
        const unsigned m_own = __match_any_sync(0xffffffffu, t);
        if (lane == (__ffs(m_own) - 1)) s_cnt[t * CNT_S + chunk] = __popc(m_own);
        myrank[j] = __popc(m_own & ((1u << lane) - 1u));
    }
    __syncthreads();

    // ---- pass 2: 128-wide scan per task via shfl warp-scan ----
    {
        const int u = tid >> 7;
        const int c = tid & 127;
        const int wir = c >> 5;
        const int orig = s_cnt[u * CNT_S + c];
        int v = orig;
#pragma unroll
        for (int off = 1; off < 32; off <<= 1) {
            const int tv = __shfl_up_sync(0xffffffffu, v, off);
            if (lane >= off) v += tv;
        }
        if (lane == 31) s_wt[u][wir] = v;
        __syncthreads();
        int add = 0;
#pragma unroll
        for (int j2 = 0; j2 < 3; j2++) if (wir > j2) add += s_wt[u][j2];
        s_excl[u * CNT_S + c] = v + add - orig;
        if (c == 127) s_tot[u] = v + add;
    }
    __syncthreads();

    // ---- pass 3: per-task bases + group table (TR=64 groups) ----
    if (tid < TT) {
        int eb = 0, gb = 0;
        for (int u = 0; u < tid; u++) {
            const int g = (s_tot[u] + TR - 1) / TR;
            gb += g; eb += g * TR;
        }
        base[tid]  = eb;
        gbase[tid] = gb;
        ngr[tid]   = (s_tot[tid] + TR - 1) / TR;
    }
    __syncthreads();

    if (tid < MAXG) {
        int val = -1;
#pragma unroll
        for (int t = 0; t < TT; t++)
            if (tid >= gbase[t] && tid < gbase[t] + ngr[t]) val = t;
        g_gtask[tid] = val;
    }

    // pad-only init: at most 63 slots per task
    if (tid < TT * TR) {
        const int tt = tid >> 6, k = tid & 63;
        const int c = s_tot[tt];
        if (k < ngr[tt] * TR - c) g_perm[base[tt] + c + k] = -1;
    }

    // ---- pass 4: direct scatter, no atomics ----
#pragma unroll
    for (int j = 0; j < NN / 1024; j++) {
        const int r = j * 1024 + tid;
        const int t = myt[j];
        const int chunk = j * 32 + wid;
        g_perm[base[t] + s_excl[t * CNT_S + chunk] + myrank[j]] = r;
    }
}

// ---------------------------------------------------------------------------
// Main: one CTA = 64 rows (same task t) x 128 columns, 512 threads, 4 CTAs/SM.
// Per-tile fixed costs (match check, compaction, xx/B gather, barriers)
// amortized over 2x rows vs the 32-row version.
//  - warps 0-3: own-ballot column compaction (CNT <= 128)
//  - compute: 16 warps; half = w>>3 picks rows 0-31 / 32-63, m = (w&7)+8k
//  - exponent = A_r + B_c + u_r . xx_c : 8 FFMA + FADD + EX2 per matched cell
//  - compact smem staging; zeros assembled in registers -> 512B STG.128
// ---------------------------------------------------------------------------
__global__ __launch_bounds__(512, 4) void rbf_main(
    const float* __restrict__ xx,
    const int*  __restrict__ ii,
    float* __restrict__ out)
{
    const int g = blockIdx.y;
    const int t = g_gtask[g];
    if (t < 0) return;

    const int c0   = blockIdx.x * TCW;
    const int tid  = threadIdx.x;
    const int lane = tid & 31;
    const int w    = tid >> 5;          // 0..15

    __shared__ __align__(16) int s_midx[TCW];  // col -> compact idx or -1
    __shared__ int   s_mcol[TCW];              // compact idx -> col
    __shared__ int   s_wcnt[4];
    __shared__ int   s_rows[TR];
    __shared__ float s_A[TR];
    __shared__ float s_uT[DIMC * UT_S];        // u transposed [d][row]
    __shared__ float s_xc[TCW * DIMC];         // compact xx rows (4 KB)
    __shared__ float s_B[TCW];                 // compact B values
    __shared__ float s_tc[TR * TCS];           // compact values [row][m] (33 KB)

    // warps 0-3: column match check (warp w owns cols w*32..w*32+31)
    unsigned bal = 0;
    bool match = false;
    if (w < 4) {
        const int col = w * 32 + lane;
        match = (ii[c0 + col] == t);
        bal = __ballot_sync(0xffffffffu, match);
        if (lane == 0) s_wcnt[w] = __popc(bal);
    }

    // u-row + A gather (8 threads per row, broadcast perm read)
    {
        const int r = tid >> 3;                 // 0..63
        const int d = tid & 7;
        const int row = g_perm[g * TR + r];
        if (d == 0) {
            s_rows[r] = row;
            s_A[r] = (row >= 0) ? g_A2[row] : 0.0f;
        }
        s_uT[d * UT_S + r] = (row >= 0) ? g_u[row * DIMC + d] : 0.0f;
    }
    __syncthreads();

    const int b0 = s_wcnt[0], b1 = s_wcnt[1], b2 = s_wcnt[2], b3 = s_wcnt[3];
    const int CNT = b0 + b1 + b2 + b3;
    if (w < 4) {
        const int col = w * 32 + lane;
        const int basew = (w >= 1 ? b0 : 0) + (w >= 2 ? b1 : 0) + (w >= 3 ? b2 : 0);
        const int midx = match ? basew + __popc(bal & ((1u << lane) - 1u)) : -1;
        s_midx[col] = midx;
        if (match) s_mcol[midx] = col;
    }
    __syncthreads();

    // gather xx + B for matched columns only
    {
        const int d = tid & 7;
        for (int m = tid >> 3; m < CNT; m += 64) {
            const int c = s_mcol[m];
            s_xc[m * DIMC + d] = xx[(c0 + c) * DIMC + d];
            if (d == 0) s_B[m] = g_B[t * MM + c0 + c];
        }
    }
    __syncthreads();

    // compute: warp w -> rows (w>>3)*32 + lane, compact cols m = (w&7), +8...
    if (CNT > 0) {
        const int row = (w >> 3) * 32 + lane;
        const float A = s_A[row];
        const float u0 = s_uT[0 * UT_S + row], u1 = s_uT[1 * UT_S + row];
        const float u2 = s_uT[2 * UT_S + row], u3 = s_uT[3 * UT_S + row];
        const float u4 = s_uT[4 * UT_S + row], u5 = s_uT[5 * UT_S + row];
        const float u6 = s_uT[6 * UT_S + row], u7 = s_uT[7 * UT_S + row];

        for (int m = (w & 7); m < CNT; m += 8) {
            const float4 xa = *(const float4*)&s_xc[m * DIMC + 0];  // broadcast
            const float4 xb = *(const float4*)&s_xc[m * DIMC + 4];
            float sum = fmaf(u0, xa.x, A);
            sum = fmaf(u1, xa.y, sum);
            sum = fmaf(u2, xa.z, sum);
            sum = fmaf(u3, xa.w, sum);
            sum = fmaf(u4, xb.x, sum);
            sum = fmaf(u5, xb.y, sum);
            sum = fmaf(u6, xb.z, sum);
            sum = fmaf(u7, xb.w, sum);
            // banks (row + m) % 32 -> conflict-free within warp
            s_tc[row * TCS + m] = exp2f(sum + s_B[m]);
        }
    }
    __syncthreads();

    // write: warp w -> rows 4w..4w+3; lane -> cols 4*lane..4*lane+3
    const int4 mi = ((const int4*)s_midx)[lane];  // LDS.128, conflict-free
#pragma unroll
    for (int rr = 0; rr < 4; rr++) {
        const int r = w * 4 + rr;
        const int row = s_rows[r];
        if (row >= 0) {
            float4 o = make_float4(0.f, 0.f, 0.f, 0.f);
            const int rb = r * TCS;
            if (mi.x >= 0) o.x = s_tc[rb + mi.x];  // distinct midx -> no conflicts
            if (mi.y >= 0) o.y = s_tc[rb + mi.y];
            if (mi.z >= 0) o.z = s_tc[rb + mi.z];
            if (mi.w >= 0) o.w = s_tc[rb + mi.w];
            *(float4*)&out[(long)row * MM + c0 + lane * 4] = o;
        }
    }
}

// ---------------------------------------------------------------------------
extern "C" void kernel_launch(void* const* d_in, const int* in_sizes, int n_in,
                              void* d_out, int out_size)
{
    const float* x     = (const float*)d_in[0];
    const float* xx    = (const float*)d_in[1];
    const float* scale = (const float*)d_in[2];
    const float* var   = (const float*)d_in[3];
    const int*   i_t   = (const int*)d_in[4];
    const int*   ii_t  = (const int*)d_in[5];
    float* out = (float*)d_out;

    rbf_prep<<<9, 1024>>>(i_t, scale, var, x, xx);

    dim3 grid(MM / TCW, MAXG);
    rbf_main<<<grid, 512>>>(xx, ii_t, out);
}

// round 14
// speedup vs baseline: 1.4901x; 1.1557x over previous
#include <cuda_runtime.h>
#include <cuda_bf16.h>
#include <cstdint>

// Problem shape (fixed by the dataset): N=M=4096, DIM=8, TASKS=8
constexpr int NN   = 4096;
constexpr int MM   = 4096;
constexpr int DIMC = 8;
constexpr int TT   = 8;

constexpr int TR  = 32;     // rows per group (== warp size)
constexpr int TCW = 128;    // columns per tile
constexpr int TCS = 129;    // compact-tile stride (odd -> conflict-free)
constexpr int XT_S = 33;    // u-transposed stride
constexpr int MAXG = 136;   // >= floor(4096/32) + (TASKS-1) = 135
constexpr int CNT_S = 129;  // sort count-array stride

// Scratch (no cudaMalloc allowed)
__device__ int   g_perm[MAXG * TR];   // row indices grouped by task, -1 = pad
__device__ int   g_gtask[MAXG];       // task id per group, -1 = unused
__device__ float g_u[NN * DIMC];      // -2*inv2[t_r][d]*x[r][d]
__device__ float g_A2[NN];            // sum_d inv2*x^2 + log2(v[t_r])
__device__ float g_B[TT * MM];        // B[t][c] = sum_d inv2[t][d]*xx[c][d]^2

__device__ __forceinline__ float softplus_f(float a) {
    return (a > 20.0f) ? a : log1pf(__expf(a));
}

// ---------------------------------------------------------------------------
// Prep (9 CTAs x 1024 thr): CTA 8 = atomic-free counting sort (match_any +
// shfl warp-scan); CTAs 0-7 = rank-9 tables (g_u/g_A2/g_B), fully parallel.
// ---------------------------------------------------------------------------
__global__ __launch_bounds__(1024) void rbf_prep(
    const int* __restrict__ i_task,
    const float* __restrict__ scale_raw,
    const float* __restrict__ var_raw,
    const float* __restrict__ x,
    const float* __restrict__ xx)
{
    const int tid = threadIdx.x;

    if (blockIdx.x < 8) {
        // ================= tables CTAs =================
        __shared__ float s_inv2[TT * DIMC];
        __shared__ float s_lv[TT];
        if (tid < TT * DIMC) {
            const int t = tid / DIMC, d = tid % DIMC;
            const float s = softplus_f(scale_raw[t * (TT * DIMC) + t * DIMC + d]);
            s_inv2[tid] = -0.5f * 1.4426950408889634f / (s * s);  // log2(e) folded
        }
        if (tid < TT) s_lv[tid] = log2f(softplus_f(var_raw[tid * TT + tid]));
        __syncthreads();

        if (tid < 512) {
            // rows: g_u, g_A2
            const int r = blockIdx.x * 512 + tid;
            const int t = i_task[r];
            const float4 a = *(const float4*)&x[r * DIMC + 0];
            const float4 b = *(const float4*)&x[r * DIMC + 4];
            float iv[DIMC];
#pragma unroll
            for (int d = 0; d < DIMC; d++) iv[d] = s_inv2[t * DIMC + d];
            float A = iv[0] * a.x * a.x;
            A = fmaf(iv[1], a.y * a.y, A); A = fmaf(iv[2], a.z * a.z, A);
            A = fmaf(iv[3], a.w * a.w, A); A = fmaf(iv[4], b.x * b.x, A);
            A = fmaf(iv[5], b.y * b.y, A); A = fmaf(iv[6], b.z * b.z, A);
            A = fmaf(iv[7], b.w * b.w, A);
            g_A2[r] = A + s_lv[t];
            *(float4*)&g_u[r * DIMC + 0] =
                make_float4(-2.f * iv[0] * a.x, -2.f * iv[1] * a.y,
                            -2.f * iv[2] * a.z, -2.f * iv[3] * a.w);
            *(float4*)&g_u[r * DIMC + 4] =
                make_float4(-2.f * iv[4] * b.x, -2.f * iv[5] * b.y,
                            -2.f * iv[6] * b.z, -2.f * iv[7] * b.w);
        } else {
            // cols: g_B for all 8 tasks
            const int c = blockIdx.x * 512 + (tid - 512);
            const float4 a = *(const float4*)&xx[c * DIMC + 0];
            const float4 b = *(const float4*)&xx[c * DIMC + 4];
            const float q0 = a.x * a.x, q1 = a.y * a.y, q2 = a.z * a.z, q3 = a.w * a.w;
            const float q4 = b.x * b.x, q5 = b.y * b.y, q6 = b.z * b.z, q7 = b.w * b.w;
#pragma unroll
            for (int t = 0; t < TT; t++) {
                float B = s_inv2[t * DIMC + 0] * q0;
                B = fmaf(s_inv2[t * DIMC + 1], q1, B);
                B = fmaf(s_inv2[t * DIMC + 2], q2, B);
                B = fmaf(s_inv2[t * DIMC + 3], q3, B);
                B = fmaf(s_inv2[t * DIMC + 4], q4, B);
                B = fmaf(s_inv2[t * DIMC + 5], q5, B);
                B = fmaf(s_inv2[t * DIMC + 6], q6, B);
                B = fmaf(s_inv2[t * DIMC + 7], q7, B);
                g_B[t * MM + c] = B;
            }
        }
        return;
    }

    // ================= sort CTA =================
    __shared__ int s_cnt[TT * CNT_S];
    __shared__ int s_excl[TT * CNT_S];
    __shared__ int s_wt[TT][4];
    __shared__ int s_tot[TT];
    __shared__ int base[TT];
    __shared__ int gbase[TT];
    __shared__ int ngr[TT];

    const int lane = tid & 31;
    const int wid  = tid >> 5;

    // zero counts (match_any stores only present tasks)
    if (tid < TT * CNT_S) s_cnt[tid] = 0;
    if (tid >= 1024 - 8) s_cnt[TT * CNT_S - (1024 - tid)] = 0;  // tail (1032>1024)
    __syncthreads();

    // ---- pass 1: per-chunk counts via match_any + own rank-in-chunk ----
    int myt[NN / 1024];
    int myrank[NN / 1024];
#pragma unroll
    for (int j = 0; j < NN / 1024; j++) {
        const int t = i_task[j * 1024 + tid];
        myt[j] = t;
        const int chunk = j * 32 + wid;
        const unsigned m_own = __match_any_sync(0xffffffffu, t);
        if (lane == (__ffs(m_own) - 1)) s_cnt[t * CNT_S + chunk] = __popc(m_own);
        myrank[j] = __popc(m_own & ((1u << lane) - 1u));
    }
    __syncthreads();

    // ---- pass 2: 128-wide scan per task via shfl warp-scan ----
    {
        const int u = tid >> 7;
        const int c = tid & 127;
        const int wir = c >> 5;
        const int orig = s_cnt[u * CNT_S + c];
        int v = orig;
#pragma unroll
        for (int off = 1; off < 32; off <<= 1) {
            const int tv = __shfl_up_sync(0xffffffffu, v, off);
            if (lane >= off) v += tv;
        }
        if (lane == 31) s_wt[u][wir] = v;
        __syncthreads();
        int add = 0;
#pragma unroll
        for (int j2 = 0; j2 < 3; j2++) if (wir > j2) add += s_wt[u][j2];
        s_excl[u * CNT_S + c] = v + add - orig;
        if (c == 127) s_tot[u] = v + add;
    }
    __syncthreads();

    // ---- pass 3: per-task bases + group table ----
    if (tid < TT) {
        int eb = 0, gb = 0;
        for (int u = 0; u < tid; u++) {
            const int g = (s_tot[u] + TR - 1) / TR;
            gb += g; eb += g * TR;
        }
        base[tid]  = eb;
        gbase[tid] = gb;
        ngr[tid]   = (s_tot[tid] + TR - 1) / TR;
    }
    __syncthreads();

    if (tid < MAXG) {
        int val = -1;
#pragma unroll
        for (int t = 0; t < TT; t++)
            if (tid >= gbase[t] && tid < gbase[t] + ngr[t]) val = t;
        g_gtask[tid] = val;
    }

    // pad-only init: at most 31 slots per task
    if (tid < TT * TR) {
        const int tt = tid >> 5, k = tid & 31;
        const int c = s_tot[tt];
        if (k < ngr[tt] * TR - c) g_perm[base[tt] + c + k] = -1;
    }

    // ---- pass 4: direct scatter, no atomics ----
#pragma unroll
    for (int j = 0; j < NN / 1024; j++) {
        const int r = j * 1024 + tid;
        const int t = myt[j];
        const int chunk = j * 32 + wid;
        g_perm[base[t] + s_excl[t * CNT_S + chunk] + myrank[j]] = r;
    }
}

// ---------------------------------------------------------------------------
// Main: one CTA = 32 rows (same task t) x 128 columns, 256 thr, 8 CTAs/SM.
// Phase A (all loads, dependency-free): match check, dense s_xx, dense s_B,
//   permuted u/A row gather. The compact xx/B gather phase is gone
//   (compute reads dense arrays via s_mcol). 3 barriers total (was 4).
// ---------------------------------------------------------------------------
__global__ __launch_bounds__(256, 8) void rbf_main(
    const float* __restrict__ xx,
    const int*  __restrict__ ii,
    float* __restrict__ out)
{
    const int g = blockIdx.y;
    const int t = g_gtask[g];
    if (t < 0) return;

    const int c0   = blockIdx.x * TCW;
    const int tid  = threadIdx.x;
    const int lane = tid & 31;
    const int w    = tid >> 5;

    __shared__ __align__(16) int s_midx[TCW];  // col -> compact idx or -1
    __shared__ int   s_mcol[TCW];              // compact idx -> col
    __shared__ int   s_wcnt[4];
    __shared__ int   s_rows[TR];
    __shared__ float s_A[TR];
    __shared__ float s_uT[DIMC * XT_S];        // u transposed [d][row]
    __shared__ float s_xx[TCW * DIMC];         // dense xx tile (4 KB)
    __shared__ float s_B[TCW];                 // dense B tile
    __shared__ float s_tc[TR * TCS];           // compact values [row][m] (16.5 KB)

    // ---------------- phase A: all independent loads ----------------
    unsigned bal = 0;
    bool match = false;
    if (w < 4) {
        const int col = w * 32 + lane;
        match = (ii[c0 + col] == t);
        bal = __ballot_sync(0xffffffffu, match);
        if (lane == 0) s_wcnt[w] = __popc(bal);
    }

    // dense xx tile: 1 float4 per thread, coalesced
    ((float4*)s_xx)[tid] = ((const float4*)(xx + c0 * DIMC))[tid];
    // dense B tile: threads 0-127, coalesced
    if (tid < TCW) s_B[tid] = g_B[t * MM + c0 + tid];

    // u-row + A gather (8 threads per row, broadcast perm read)
    {
        const int r = tid >> 3;
        const int d = tid & 7;
        const int row = g_perm[g * TR + r];
        if (d == 0) {
            s_rows[r] = row;
            s_A[r] = (row >= 0) ? g_A2[row] : 0.0f;
        }
        s_uT[d * XT_S + r] = (row >= 0) ? g_u[row * DIMC + d] : 0.0f;
    }
    __syncthreads();

    // ---------------- phase B: compaction (warps 0-3) ----------------
    const int b0 = s_wcnt[0], b1 = s_wcnt[1], b2 = s_wcnt[2], b3 = s_wcnt[3];
    const int CNT = b0 + b1 + b2 + b3;
    if (w < 4) {
        const int col = w * 32 + lane;
        const int basew = (w >= 1 ? b0 : 0) + (w >= 2 ? b1 : 0) + (w >= 3 ? b2 : 0);
        const int midx = match ? basew + __popc(bal & ((1u << lane) - 1u)) : -1;
        s_midx[col] = midx;
        if (match) s_mcol[midx] = col;
    }
    __syncthreads();

    // ---------------- phase C: compute (lanes = rows) ----------------
    if (CNT > 0) {
        const float A = s_A[lane];
        const float u0 = s_uT[0 * XT_S + lane], u1 = s_uT[1 * XT_S + lane];
        const float u2 = s_uT[2 * XT_S + lane], u3 = s_uT[3 * XT_S + lane];
        const float u4 = s_uT[4 * XT_S + lane], u5 = s_uT[5 * XT_S + lane];
        const float u6 = s_uT[6 * XT_S + lane], u7 = s_uT[7 * XT_S + lane];

        int m = w;
        // unrolled-by-2 main loop (typical trip count is 2)
        for (; m + 8 < CNT; m += 16) {
            const int ca = s_mcol[m];
            const int cb = s_mcol[m + 8];
            const float4 xa0 = *(const float4*)&s_xx[ca * DIMC + 0];
            const float4 xb0 = *(const float4*)&s_xx[ca * DIMC + 4];
            const float4 xa1 = *(const float4*)&s_xx[cb * DIMC + 0];
            const float4 xb1 = *(const float4*)&s_xx[cb * DIMC + 4];
            float s0 = fmaf(u0, xa0.x, A);
            float s1 = fmaf(u0, xa1.x, A);
            s0 = fmaf(u1, xa0.y, s0);  s1 = fmaf(u1, xa1.y, s1);
            s0 = fmaf(u2, xa0.z, s0);  s1 = fmaf(u2, xa1.z, s1);
            s0 = fmaf(u3, xa0.w, s0);  s1 = fmaf(u3, xa1.w, s1);
            s0 = fmaf(u4, xb0.x, s0);  s1 = fmaf(u4, xb1.x, s1);
            s0 = fmaf(u5, xb0.y, s0);  s1 = fmaf(u5, xb1.y, s1);
            s0 = fmaf(u6, xb0.z, s0);  s1 = fmaf(u6, xb1.z, s1);
            s0 = fmaf(u7, xb0.w, s0);  s1 = fmaf(u7, xb1.w, s1);
            s_tc[lane * TCS + m]     = exp2f(s0 + s_B[ca]);
            s_tc[lane * TCS + m + 8] = exp2f(s1 + s_B[cb]);
        }
        if (m < CNT) {
            const int c = s_mcol[m];
            const float4 xa = *(const float4*)&s_xx[c * DIMC + 0];
            const float4 xb = *(const float4*)&s_xx[c * DIMC + 4];
            float sum = fmaf(u0, xa.x, A);
            sum = fmaf(u1, xa.y, sum);
            sum = fmaf(u2, xa.z, sum);
            sum = fmaf(u3, xa.w, sum);
            sum = fmaf(u4, xb.x, sum);
            sum = fmaf(u5, xb.y, sum);
            sum = fmaf(u6, xb.z, sum);
            sum = fmaf(u7, xb.w, sum);
            s_tc[lane * TCS + m] = exp2f(sum + s_B[c]);
        }
    }
    __syncthreads();

    // ---------------- phase D: write (warp w -> rows 4w..4w+3) ----------------
    const int4 mi = ((const int4*)s_midx)[lane];  // LDS.128, conflict-free
#pragma unroll
    for (int rr = 0; rr < 4; rr++) {
        const int r = w * 4 + rr;
        const int row = s_rows[r];
        if (row >= 0) {
            float4 o = make_float4(0.f, 0.f, 0.f, 0.f);
            const int rb = r * TCS;
            if (mi.x >= 0) o.x = s_tc[rb + mi.x];  // distinct midx -> few conflicts
            if (mi.y >= 0) o.y = s_tc[rb + mi.y];
            if (mi.z >= 0) o.z = s_tc[rb + mi.z];
            if (mi.w >= 0) o.w = s_tc[rb + mi.w];
            *(float4*)&out[(long)row * MM + c0 + lane * 4] = o;
        }
    }
}

// ---------------------------------------------------------------------------
extern "C" void kernel_launch(void* const* d_in, const int* in_sizes, int n_in,
                              void* d_out, int out_size)
{
    const float* x     = (const float*)d_in[0];
    const float* xx    = (const float*)d_in[1];
    const float* scale = (const float*)d_in[2];
    const float* var   = (const float*)d_in[3];
    const int*   i_t   = (const int*)d_in[4];
    const int*   ii_t  = (const int*)d_in[5];
    float* out = (float*)d_out;

    rbf_prep<<<9, 1024>>>(i_t, scale, var, x, xx);

    dim3 grid(MM / TCW, MAXG);
    rbf_main<<<grid, 256>>>(xx, ii_t, out);
}